// round 12
// baseline (speedup 1.0000x reference)
#include <cuda_runtime.h>
#include <cuda_bf16.h>
#include <cstdint>
#include <math_constants.h>

#define HEADS 8
#define HD 32
#define NTOK 49
#define DIM 256
#define BATCH 2048
#define NWIN 64

// scratch (allocation-free rule: device globals)
__device__ float g_qkv[(size_t)BATCH * NTOK * 3 * DIM];      // [B, N, 768]
__device__ float g_ao[(size_t)BATCH * NTOK * DIM];           // attention out (tf32-rounded)
__device__ float g_wq[DIM * 3 * DIM];                        // tf32(qkv_w)
__device__ float g_wp[DIM * DIM];                            // tf32(proj_w)
__device__ float g_comb[(size_t)NWIN * HEADS * NTOK * NTOK]; // [w][h][i][j]

__device__ __forceinline__ uint32_t f2tf32(float x) {
    uint32_t u;
    asm("cvt.rna.tf32.f32 %0, %1;" : "=r"(u) : "f"(x));
    return u;
}

__device__ __forceinline__ void mma_tf32(float* c, const uint32_t* a, const uint32_t* b) {
    asm volatile(
        "mma.sync.aligned.m16n8k8.row.col.f32.tf32.tf32.f32 "
        "{%0,%1,%2,%3}, {%4,%5,%6,%7}, {%8,%9}, {%0,%1,%2,%3};"
        : "+f"(c[0]), "+f"(c[1]), "+f"(c[2]), "+f"(c[3])
        : "r"(a[0]), "r"(a[1]), "r"(a[2]), "r"(a[3]), "r"(b[0]), "r"(b[1]));
}

__device__ __forceinline__ void mma_bf16(float* c, const uint32_t* a, const uint32_t* b) {
    asm volatile(
        "mma.sync.aligned.m16n8k16.row.col.f32.bf16.bf16.f32 "
        "{%0,%1,%2,%3}, {%4,%5,%6,%7}, {%8,%9}, {%0,%1,%2,%3};"
        : "+f"(c[0]), "+f"(c[1]), "+f"(c[2]), "+f"(c[3])
        : "r"(a[0]), "r"(a[1]), "r"(a[2]), "r"(a[3]), "r"(b[0]), "r"(b[1]));
}

__device__ __forceinline__ void split_pack_bf16(float x, float y,
                                                uint32_t& hi, uint32_t& lo) {
    __nv_bfloat16 hx = __float2bfloat16(x);
    __nv_bfloat16 hy = __float2bfloat16(y);
    __nv_bfloat16 lx = __float2bfloat16(x - __bfloat162float(hx));
    __nv_bfloat16 ly = __float2bfloat16(y - __bfloat162float(hy));
    __nv_bfloat162 h; h.x = hx; h.y = hy;
    __nv_bfloat162 l; l.x = lx; l.y = ly;
    hi = *(uint32_t*)&h;
    lo = *(uint32_t*)&l;
}

__device__ __forceinline__ void cp16(uint32_t smem_dst, const void* gptr) {
    asm volatile("cp.async.cg.shared.global [%0], [%1], 16;\n"
                 :: "r"(smem_dst), "l"(gptr));
}

// ---------------------------------------------------------------------------
// Elementwise tf32 rounding pass (weights only)
// ---------------------------------------------------------------------------
__global__ __launch_bounds__(256) void cvt_tf32_kernel(
    const float4* __restrict__ src, float4* __restrict__ dst, int n4)
{
    for (int i = blockIdx.x * 256 + threadIdx.x; i < n4; i += gridDim.x * 256) {
        float4 v = src[i];
        float4 o;
        o.x = __uint_as_float(f2tf32(v.x));
        o.y = __uint_as_float(f2tf32(v.y));
        o.z = __uint_as_float(f2tf32(v.z));
        o.w = __uint_as_float(f2tf32(v.w));
        dst[i] = o;
    }
}

// ---------------------------------------------------------------------------
// TF32 mma.sync GEMM, cp.async double-buffered.
// BM=128, BN=128, BK=32, 256 threads (8 warps 2x4), warp tile 64x32.
// smem: 2 stages x (128*36 + 32*136) floats = 71680 B -> 2 CTAs/SM, 16 warps.
// ---------------------------------------------------------------------------
#define GEMM_STAGE_FLOATS (128 * 36 + 32 * 136)
#define GEMM_SMEM_BYTES (2 * GEMM_STAGE_FLOATS * 4)

template<bool CVT_A>
__global__ __launch_bounds__(256) void gemm_tf32_w64(
    const float* __restrict__ A, const float* __restrict__ B,
    const float* __restrict__ bias, float* __restrict__ C,
    int M, int N, int K)
{
    constexpr int ASTR = 36, BSTR = 136;

    extern __shared__ float sm[];

    const int tid = threadIdx.x;
    const int wid = tid >> 5;
    const int lane = tid & 31;
    const int lr = lane >> 2;
    const int lc = lane & 3;
    const int wm = wid & 1;     // 2 m-tiles of 64
    const int wn = wid >> 1;    // 4 n-tiles of 32

    const int bm = blockIdx.y * 128;
    const int bn = blockIdx.x * 128;

    const uint32_t smem_base = (uint32_t)__cvta_generic_to_shared(sm);

    // issue one K-tile (128x32 A, 32x128 B) into stage s
    auto issue = [&](int k0, int s) {
        const uint32_t as_base = smem_base + (uint32_t)(s * GEMM_STAGE_FLOATS) * 4;
        const uint32_t bs_base = as_base + 128 * ASTR * 4;
        #pragma unroll
        for (int i = 0; i < 4; i++) {
            const int idx = tid + 256 * i;
            const int r = idx >> 3, c4 = idx & 7;
            cp16(as_base + (r * ASTR + c4 * 4) * 4,
                 A + (size_t)(bm + r) * K + k0 + c4 * 4);
        }
        #pragma unroll
        for (int i = 0; i < 4; i++) {
            const int idx = tid + 256 * i;
            const int r = idx >> 5, c4 = idx & 31;
            cp16(bs_base + (r * BSTR + c4 * 4) * 4,
                 B + (size_t)(k0 + r) * N + bn + c4 * 4);
        }
        asm volatile("cp.async.commit_group;\n" ::);
    };

    float acc[4][4][4] = {};   // [mi][ni][frag]

    const int niter = K / 32;
    issue(0, 0);
    if (niter > 1) issue(32, 1);

    for (int it = 0; it < niter; it++) {
        if (it < niter - 1)
            asm volatile("cp.async.wait_group 1;\n" ::);
        else
            asm volatile("cp.async.wait_group 0;\n" ::);
        __syncthreads();

        const float* As = sm + (it & 1) * GEMM_STAGE_FLOATS;
        const float* Bs = As + 128 * ASTR;

        #pragma unroll
        for (int ks = 0; ks < 4; ks++) {
            const int k = ks * 8;
            uint32_t afr[4][4];
            #pragma unroll
            for (int mi = 0; mi < 4; mi++) {
                const int r = wm * 64 + mi * 16;
                if (CVT_A) {
                    afr[mi][0] = f2tf32(As[(r + lr) * ASTR + k + lc]);
                    afr[mi][1] = f2tf32(As[(r + 8 + lr) * ASTR + k + lc]);
                    afr[mi][2] = f2tf32(As[(r + lr) * ASTR + k + 4 + lc]);
                    afr[mi][3] = f2tf32(As[(r + 8 + lr) * ASTR + k + 4 + lc]);
                } else {
                    afr[mi][0] = __float_as_uint(As[(r + lr) * ASTR + k + lc]);
                    afr[mi][1] = __float_as_uint(As[(r + 8 + lr) * ASTR + k + lc]);
                    afr[mi][2] = __float_as_uint(As[(r + lr) * ASTR + k + 4 + lc]);
                    afr[mi][3] = __float_as_uint(As[(r + 8 + lr) * ASTR + k + 4 + lc]);
                }
            }
            uint32_t bfr[4][2];
            #pragma unroll
            for (int ni = 0; ni < 4; ni++) {
                const int c = wn * 32 + ni * 8 + lr;
                bfr[ni][0] = __float_as_uint(Bs[(k + lc) * BSTR + c]);
                bfr[ni][1] = __float_as_uint(Bs[(k + 4 + lc) * BSTR + c]);
            }
            #pragma unroll
            for (int mi = 0; mi < 4; mi++)
                #pragma unroll
                for (int ni = 0; ni < 4; ni++)
                    mma_tf32(acc[mi][ni], afr[mi], bfr[ni]);
        }
        __syncthreads();

        if (it + 2 < niter) issue((it + 2) * 32, it & 1);
    }

    // epilogue
    #pragma unroll
    for (int mi = 0; mi < 4; mi++) {
        #pragma unroll
        for (int ni = 0; ni < 4; ni++) {
            const int r0 = bm + wm * 64 + mi * 16 + lr;
            const int c0 = bn + wn * 32 + ni * 8 + lc * 2;
            float2 b01 = *(const float2*)(bias + c0);
            float2 v0 = make_float2(acc[mi][ni][0] + b01.x, acc[mi][ni][1] + b01.y);
            float2 v1 = make_float2(acc[mi][ni][2] + b01.x, acc[mi][ni][3] + b01.y);
            *(float2*)(C + (size_t)r0 * N + c0) = v0;
            *(float2*)(C + (size_t)(r0 + 8) * N + c0) = v1;
        }
    }
}

// ---------------------------------------------------------------------------
// comb[w][h][i][j] = mask[w][i][j] + bias_table[rel_index[i*49+j]][h]
// ---------------------------------------------------------------------------
__global__ __launch_bounds__(256) void comb_kernel(
    const float* __restrict__ mask, const float* __restrict__ bias_table,
    const int* __restrict__ rel_index, float* __restrict__ comb)
{
    const int total = NWIN * HEADS * NTOK * NTOK;
    int idx = blockIdx.x * 256 + threadIdx.x;
    if (idx < total) {
        const int ij = idx % (NTOK * NTOK);
        const int wh = idx / (NTOK * NTOK);
        const int h = wh & (HEADS - 1);
        const int w = wh >> 3;
        comb[idx] = mask[w * NTOK * NTOK + ij] + bias_table[rel_index[ij] * HEADS + h];
    }
}

// ---------------------------------------------------------------------------
// Register-resident-softmax bf16 attention (round-8 known good).
// ---------------------------------------------------------------------------
__global__ __launch_bounds__(128) void attn_reg_kernel(
    const float* __restrict__ qkv,       // [B, N, 768]
    const float* __restrict__ comb,      // [64][8][49][49]
    float* __restrict__ out)             // [B, N, 256] (tf32-rounded)
{
    __shared__ __align__(16) uint32_t sw[7104];
    uint32_t* Qh  = sw;            // 64 x 20
    uint32_t* Ql  = sw + 1280;
    uint32_t* Kh  = sw + 2560;     // 56 x 20
    uint32_t* Kl  = sw + 3680;
    uint32_t* Vth = sw + 4800;     // 32 x 36 (V transposed [d][j])
    uint32_t* Vtl = sw + 5952;

    const int b = blockIdx.x;
    const int h = blockIdx.y;
    const int tid = threadIdx.x;
    const int wid = tid >> 5;
    const int lane = tid & 31;
    const int lr = lane >> 2;
    const int lc = lane & 3;

    const float scale = 0.17677669529663687f;
    const float* base = qkv + (size_t)b * NTOK * 3 * DIM + h * HD;

    {
        __nv_bfloat16* vhH = (__nv_bfloat16*)Vth;
        __nv_bfloat16* vlH = (__nv_bfloat16*)Vtl;
        for (int e = tid; e < HD * 15; e += 128) {
            const int d = e / 15;
            const int j = NTOK + (e % 15);
            vhH[d * 72 + j] = __float2bfloat16(0.f);
            vlH[d * 72 + j] = __float2bfloat16(0.f);
        }
        for (int pe = tid; pe < NTOK * (HD / 2); pe += 128) {
            const int n = pe >> 4;
            const int dp = pe & 15;
            const int d = dp * 2;
            const float* row = base + (size_t)n * (3 * DIM) + d;
            float2 q2 = *(const float2*)(row);
            float2 k2 = *(const float2*)(row + DIM);
            float2 v2 = *(const float2*)(row + 2 * DIM);
            q2.x *= scale; q2.y *= scale;

            uint32_t hi, lo;
            split_pack_bf16(q2.x, q2.y, hi, lo);
            Qh[n * 20 + dp] = hi;
            Ql[n * 20 + dp] = lo;
            split_pack_bf16(k2.x, k2.y, hi, lo);
            Kh[n * 20 + dp] = hi;
            Kl[n * 20 + dp] = lo;

            __nv_bfloat16 vh0 = __float2bfloat16(v2.x);
            __nv_bfloat16 vh1 = __float2bfloat16(v2.y);
            __nv_bfloat16 vl0 = __float2bfloat16(v2.x - __bfloat162float(vh0));
            __nv_bfloat16 vl1 = __float2bfloat16(v2.y - __bfloat162float(vh1));
            vhH[d * 72 + n] = vh0;
            vhH[(d + 1) * 72 + n] = vh1;
            vlH[d * 72 + n] = vl0;
            vlH[(d + 1) * 72 + n] = vl1;
        }
    }
    __syncthreads();

    const int mr = wid * 16;

    float sacc[7][4] = {};
    #pragma unroll
    for (int kt = 0; kt < 2; kt++) {
        const int kw = kt * 8;
        uint32_t ah[4], al[4];
        ah[0] = Qh[(mr + lr) * 20 + kw + lc];
        ah[1] = Qh[(mr + 8 + lr) * 20 + kw + lc];
        ah[2] = Qh[(mr + lr) * 20 + kw + 4 + lc];
        ah[3] = Qh[(mr + 8 + lr) * 20 + kw + 4 + lc];
        al[0] = Ql[(mr + lr) * 20 + kw + lc];
        al[1] = Ql[(mr + 8 + lr) * 20 + kw + lc];
        al[2] = Ql[(mr + lr) * 20 + kw + 4 + lc];
        al[3] = Ql[(mr + 8 + lr) * 20 + kw + 4 + lc];

        #pragma unroll
        for (int nt = 0; nt < 7; nt++) {
            const int n0 = nt * 8;
            uint32_t bh[2], bl[2];
            bh[0] = Kh[(n0 + lr) * 20 + kw + lc];
            bh[1] = Kh[(n0 + lr) * 20 + kw + 4 + lc];
            bl[0] = Kl[(n0 + lr) * 20 + kw + lc];
            bl[1] = Kl[(n0 + lr) * 20 + kw + 4 + lc];
            mma_bf16(sacc[nt], ah, bh);
            mma_bf16(sacc[nt], al, bh);
            mma_bf16(sacc[nt], ah, bl);
        }
    }

    {
        const float* cb = comb + ((size_t)((b & (NWIN - 1)) * HEADS + h)) * (NTOK * NTOK);
        const int rA = mr + lr;
        const int rB = mr + 8 + lr;
        const bool okA = rA < NTOK;
        const bool okB = rB < NTOK;
        float mA = -CUDART_INF_F, mB = -CUDART_INF_F;

        #pragma unroll
        for (int nt = 0; nt < 7; nt++) {
            const int c0 = nt * 8 + 2 * lc;
            const bool ok0 = c0 < NTOK;
            const bool ok1 = (c0 + 1) < NTOK;
            float v0A = (okA && ok0) ? sacc[nt][0] + __ldg(cb + rA * NTOK + c0)     : -CUDART_INF_F;
            float v1A = (okA && ok1) ? sacc[nt][1] + __ldg(cb + rA * NTOK + c0 + 1) : -CUDART_INF_F;
            float v0B = (okB && ok0) ? sacc[nt][2] + __ldg(cb + rB * NTOK + c0)     : -CUDART_INF_F;
            float v1B = (okB && ok1) ? sacc[nt][3] + __ldg(cb + rB * NTOK + c0 + 1) : -CUDART_INF_F;
            sacc[nt][0] = v0A; sacc[nt][1] = v1A;
            sacc[nt][2] = v0B; sacc[nt][3] = v1B;
            mA = fmaxf(mA, fmaxf(v0A, v1A));
            mB = fmaxf(mB, fmaxf(v0B, v1B));
        }
        mA = fmaxf(mA, __shfl_xor_sync(0xffffffffu, mA, 1));
        mA = fmaxf(mA, __shfl_xor_sync(0xffffffffu, mA, 2));
        mB = fmaxf(mB, __shfl_xor_sync(0xffffffffu, mB, 1));
        mB = fmaxf(mB, __shfl_xor_sync(0xffffffffu, mB, 2));

        float sA = 0.f, sB = 0.f;
        #pragma unroll
        for (int nt = 0; nt < 7; nt++) {
            float e0A = __expf(sacc[nt][0] - mA);
            float e1A = __expf(sacc[nt][1] - mA);
            float e0B = __expf(sacc[nt][2] - mB);
            float e1B = __expf(sacc[nt][3] - mB);
            sacc[nt][0] = e0A; sacc[nt][1] = e1A;
            sacc[nt][2] = e0B; sacc[nt][3] = e1B;
            sA += e0A + e1A;
            sB += e0B + e1B;
        }
        sA += __shfl_xor_sync(0xffffffffu, sA, 1);
        sA += __shfl_xor_sync(0xffffffffu, sA, 2);
        sB += __shfl_xor_sync(0xffffffffu, sB, 1);
        sB += __shfl_xor_sync(0xffffffffu, sB, 2);
        const float invA = 1.f / sA;
        const float invB = 1.f / sB;
        #pragma unroll
        for (int nt = 0; nt < 7; nt++) {
            sacc[nt][0] *= invA; sacc[nt][1] *= invA;
            sacc[nt][2] *= invB; sacc[nt][3] *= invB;
        }
    }

    {
        float oacc[4][4] = {};
        #pragma unroll
        for (int kt = 0; kt < 4; kt++) {
            const int kw = kt * 8;
            const int t0 = 2 * kt;
            const int t1 = 2 * kt + 1;
            uint32_t ah[4], al[4];
            split_pack_bf16(sacc[t0][0], sacc[t0][1], ah[0], al[0]);
            split_pack_bf16(sacc[t0][2], sacc[t0][3], ah[1], al[1]);
            if (t1 < 7) {
                split_pack_bf16(sacc[t1][0], sacc[t1][1], ah[2], al[2]);
                split_pack_bf16(sacc[t1][2], sacc[t1][3], ah[3], al[3]);
            } else {
                ah[2] = ah[3] = al[2] = al[3] = 0u;
            }

            #pragma unroll
            for (int nt = 0; nt < 4; nt++) {
                const int n0 = nt * 8;
                uint32_t bh[2], bl[2];
                bh[0] = Vth[(n0 + lr) * 36 + kw + lc];
                bh[1] = Vth[(n0 + lr) * 36 + kw + 4 + lc];
                bl[0] = Vtl[(n0 + lr) * 36 + kw + lc];
                bl[1] = Vtl[(n0 + lr) * 36 + kw + 4 + lc];
                mma_bf16(oacc[nt], ah, bh);
                mma_bf16(oacc[nt], al, bh);
                mma_bf16(oacc[nt], ah, bl);
            }
        }

        const int r0 = mr + lr;
        const int r1 = mr + 8 + lr;
        #pragma unroll
        for (int nt = 0; nt < 4; nt++) {
            const int c0 = h * HD + nt * 8 + lc * 2;
            if (r0 < NTOK) {
                float2 v = make_float2(__uint_as_float(f2tf32(oacc[nt][0])),
                                       __uint_as_float(f2tf32(oacc[nt][1])));
                *(float2*)(out + ((size_t)b * NTOK + r0) * DIM + c0) = v;
            }
            if (r1 < NTOK) {
                float2 v = make_float2(__uint_as_float(f2tf32(oacc[nt][2])),
                                       __uint_as_float(f2tf32(oacc[nt][3])));
                *(float2*)(out + ((size_t)b * NTOK + r1) * DIM + c0) = v;
            }
        }
    }
}

// ---------------------------------------------------------------------------
extern "C" void kernel_launch(void* const* d_in, const int* in_sizes, int n_in,
                              void* d_out, int out_size)
{
    const float* x          = (const float*)d_in[0];
    const float* mask       = (const float*)d_in[1];
    const float* qkv_w      = (const float*)d_in[2];
    const float* qkv_b      = (const float*)d_in[3];
    const float* proj_w     = (const float*)d_in[4];
    const float* proj_b     = (const float*)d_in[5];
    const float* bias_table = (const float*)d_in[6];
    const int*   rel_index  = (const int*)d_in[7];
    float* out = (float*)d_out;

    float *qkv_buf, *ao_buf, *wq_buf, *wp_buf, *comb_buf;
    cudaGetSymbolAddress((void**)&qkv_buf, g_qkv);
    cudaGetSymbolAddress((void**)&ao_buf, g_ao);
    cudaGetSymbolAddress((void**)&wq_buf, g_wq);
    cudaGetSymbolAddress((void**)&wp_buf, g_wp);
    cudaGetSymbolAddress((void**)&comb_buf, g_comb);

    static bool attr_set = false;
    if (!attr_set) {
        cudaFuncSetAttribute(gemm_tf32_w64<true>,
                             cudaFuncAttributeMaxDynamicSharedMemorySize,
                             GEMM_SMEM_BYTES);
        cudaFuncSetAttribute(gemm_tf32_w64<false>,
                             cudaFuncAttributeMaxDynamicSharedMemorySize,
                             GEMM_SMEM_BYTES);
        attr_set = true;
    }

    const int M = BATCH * NTOK;   // 100352 = 128 * 784

    // 0a) tf32-round weights (small)
    {
        cvt_tf32_kernel<<<192, 256>>>((const float4*)qkv_w, (float4*)wq_buf,
                                      DIM * 3 * DIM / 4);
        cvt_tf32_kernel<<<64, 256>>>((const float4*)proj_w, (float4*)wp_buf,
                                     DIM * DIM / 4);
    }
    // 0b) combined bias+mask table
    {
        const int total = NWIN * HEADS * NTOK * NTOK;
        comb_kernel<<<(total + 255) / 256, 256>>>(mask, bias_table, rel_index, comb_buf);
    }
    // 1) QKV GEMM: raw f32 x, cvt in A-frag path
    {
        dim3 grid(3 * DIM / 128, M / 128);
        gemm_tf32_w64<true><<<grid, 256, GEMM_SMEM_BYTES>>>(x, wq_buf, qkv_b, qkv_buf,
                                                            M, 3 * DIM, DIM);
    }
    // 2) register-softmax attention
    {
        dim3 grid(BATCH, HEADS);
        attn_reg_kernel<<<grid, 128>>>(qkv_buf, comb_buf, ao_buf);
    }
    // 3) Proj GEMM: A already tf32-rounded
    {
        dim3 grid(DIM / 128, M / 128);
        gemm_tf32_w64<false><<<grid, 256, GEMM_SMEM_BYTES>>>(ao_buf, wp_buf, proj_b, out,
                                                             M, DIM, DIM);
    }
}

// round 13
// speedup vs baseline: 1.1415x; 1.1415x over previous
#include <cuda_runtime.h>
#include <cuda_bf16.h>
#include <cstdint>
#include <math_constants.h>

#define HEADS 8
#define HD 32
#define NTOK 49
#define DIM 256
#define BATCH 2048
#define NWIN 64

// scratch (allocation-free rule: device globals)
__device__ float g_qkv[(size_t)BATCH * NTOK * 3 * DIM];      // [B, N, 768]
__device__ float g_ao[(size_t)BATCH * NTOK * DIM];           // attention out (tf32-rounded)
__device__ float g_wq[DIM * 3 * DIM];                        // tf32(qkv_w)
__device__ float g_wp[DIM * DIM];                            // tf32(proj_w)
__device__ float g_comb[(size_t)NWIN * HEADS * NTOK * NTOK]; // [w][h][i][j]

__device__ __forceinline__ uint32_t f2tf32(float x) {
    uint32_t u;
    asm("cvt.rna.tf32.f32 %0, %1;" : "=r"(u) : "f"(x));
    return u;
}

__device__ __forceinline__ void mma_tf32(float* c, const uint32_t* a, const uint32_t* b) {
    asm volatile(
        "mma.sync.aligned.m16n8k8.row.col.f32.tf32.tf32.f32 "
        "{%0,%1,%2,%3}, {%4,%5,%6,%7}, {%8,%9}, {%0,%1,%2,%3};"
        : "+f"(c[0]), "+f"(c[1]), "+f"(c[2]), "+f"(c[3])
        : "r"(a[0]), "r"(a[1]), "r"(a[2]), "r"(a[3]), "r"(b[0]), "r"(b[1]));
}

__device__ __forceinline__ void mma_bf16(float* c, const uint32_t* a, const uint32_t* b) {
    asm volatile(
        "mma.sync.aligned.m16n8k16.row.col.f32.bf16.bf16.f32 "
        "{%0,%1,%2,%3}, {%4,%5,%6,%7}, {%8,%9}, {%0,%1,%2,%3};"
        : "+f"(c[0]), "+f"(c[1]), "+f"(c[2]), "+f"(c[3])
        : "r"(a[0]), "r"(a[1]), "r"(a[2]), "r"(a[3]), "r"(b[0]), "r"(b[1]));
}

__device__ __forceinline__ void split_pack_bf16(float x, float y,
                                                uint32_t& hi, uint32_t& lo) {
    __nv_bfloat16 hx = __float2bfloat16(x);
    __nv_bfloat16 hy = __float2bfloat16(y);
    __nv_bfloat16 lx = __float2bfloat16(x - __bfloat162float(hx));
    __nv_bfloat16 ly = __float2bfloat16(y - __bfloat162float(hy));
    __nv_bfloat162 h; h.x = hx; h.y = hy;
    __nv_bfloat162 l; l.x = lx; l.y = ly;
    hi = *(uint32_t*)&h;
    lo = *(uint32_t*)&l;
}

__device__ __forceinline__ void cp16(uint32_t smem_dst, const void* gptr) {
    asm volatile("cp.async.cg.shared.global [%0], [%1], 16;\n"
                 :: "r"(smem_dst), "l"(gptr));
}

// ---------------------------------------------------------------------------
// Elementwise tf32 rounding pass (weights only)
// ---------------------------------------------------------------------------
__global__ __launch_bounds__(256) void cvt_tf32_kernel(
    const float4* __restrict__ src, float4* __restrict__ dst, int n4)
{
    for (int i = blockIdx.x * 256 + threadIdx.x; i < n4; i += gridDim.x * 256) {
        float4 v = src[i];
        float4 o;
        o.x = __uint_as_float(f2tf32(v.x));
        o.y = __uint_as_float(f2tf32(v.y));
        o.z = __uint_as_float(f2tf32(v.z));
        o.w = __uint_as_float(f2tf32(v.w));
        dst[i] = o;
    }
}

// ---------------------------------------------------------------------------
// TF32 mma.sync GEMM, 3-stage cp.async pipeline, one barrier per K-iter.
// BM=128, BN=128, BK=32, 128 threads (4 warps 2x2), warp tile 64x64.
// smem: 3 stages x (128*36 + 32*136) floats = 107520 B -> 2 CTAs/SM.
// ---------------------------------------------------------------------------
#define GEMM_STAGE_FLOATS (128 * 36 + 32 * 136)
#define GEMM_STAGES 3
#define GEMM_SMEM_BYTES (GEMM_STAGES * GEMM_STAGE_FLOATS * 4)

template<bool CVT_A>
__global__ __launch_bounds__(128) void gemm_tf32_w64(
    const float* __restrict__ A, const float* __restrict__ B,
    const float* __restrict__ bias, float* __restrict__ C,
    int M, int N, int K)
{
    constexpr int ASTR = 36, BSTR = 136;

    extern __shared__ float sm[];

    const int tid = threadIdx.x;
    const int wid = tid >> 5;
    const int lane = tid & 31;
    const int lr = lane >> 2;
    const int lc = lane & 3;
    const int wm = wid & 1;     // 2 m-tiles of 64
    const int wn = wid >> 1;    // 2 n-tiles of 64

    const int bm = blockIdx.y * 128;
    const int bn = blockIdx.x * 128;

    const uint32_t smem_base = (uint32_t)__cvta_generic_to_shared(sm);

    // issue one K-tile (128x32 A, 32x128 B) into stage s
    auto issue = [&](int k0, int s) {
        const uint32_t as_base = smem_base + (uint32_t)(s * GEMM_STAGE_FLOATS) * 4;
        const uint32_t bs_base = as_base + 128 * ASTR * 4;
        #pragma unroll
        for (int i = 0; i < 8; i++) {
            const int idx = tid + 128 * i;
            const int r = idx >> 3, c4 = idx & 7;
            cp16(as_base + (r * ASTR + c4 * 4) * 4,
                 A + (size_t)(bm + r) * K + k0 + c4 * 4);
        }
        #pragma unroll
        for (int i = 0; i < 8; i++) {
            const int idx = tid + 128 * i;
            const int r = idx >> 5, c4 = idx & 31;
            cp16(bs_base + (r * BSTR + c4 * 4) * 4,
                 B + (size_t)(k0 + r) * N + bn + c4 * 4);
        }
        asm volatile("cp.async.commit_group;\n" ::);
    };

    float acc[4][8][4] = {};   // [mi][ni][frag]

    const int niter = K / 32;   // 8
    issue(0, 0);
    issue(32, 1);

    for (int it = 0; it < niter; it++) {
        if (it < niter - 1)
            asm volatile("cp.async.wait_group 1;\n" ::);
        else
            asm volatile("cp.async.wait_group 0;\n" ::);
        __syncthreads();

        const int s = it % GEMM_STAGES;
        const float* As = sm + s * GEMM_STAGE_FLOATS;
        const float* Bs = As + 128 * ASTR;

        #pragma unroll
        for (int ks = 0; ks < 4; ks++) {
            const int k = ks * 8;
            uint32_t afr[4][4];
            #pragma unroll
            for (int mi = 0; mi < 4; mi++) {
                const int r = wm * 64 + mi * 16;
                if (CVT_A) {
                    afr[mi][0] = f2tf32(As[(r + lr) * ASTR + k + lc]);
                    afr[mi][1] = f2tf32(As[(r + 8 + lr) * ASTR + k + lc]);
                    afr[mi][2] = f2tf32(As[(r + lr) * ASTR + k + 4 + lc]);
                    afr[mi][3] = f2tf32(As[(r + 8 + lr) * ASTR + k + 4 + lc]);
                } else {
                    afr[mi][0] = __float_as_uint(As[(r + lr) * ASTR + k + lc]);
                    afr[mi][1] = __float_as_uint(As[(r + 8 + lr) * ASTR + k + lc]);
                    afr[mi][2] = __float_as_uint(As[(r + lr) * ASTR + k + 4 + lc]);
                    afr[mi][3] = __float_as_uint(As[(r + 8 + lr) * ASTR + k + 4 + lc]);
                }
            }
            uint32_t bfr[8][2];
            #pragma unroll
            for (int ni = 0; ni < 8; ni++) {
                const int c = wn * 64 + ni * 8 + lr;
                bfr[ni][0] = __float_as_uint(Bs[(k + lc) * BSTR + c]);
                bfr[ni][1] = __float_as_uint(Bs[(k + 4 + lc) * BSTR + c]);
            }
            #pragma unroll
            for (int mi = 0; mi < 4; mi++)
                #pragma unroll
                for (int ni = 0; ni < 8; ni++)
                    mma_tf32(acc[mi][ni], afr[mi], bfr[ni]);
        }

        // re-issue into stage (it+2)%3 == stage last read at it-1; the barrier
        // at the top of this iteration ordered all those reads before us.
        if (it + 2 < niter) issue((it + 2) * 32, (it + 2) % GEMM_STAGES);
    }

    // epilogue
    #pragma unroll
    for (int mi = 0; mi < 4; mi++) {
        #pragma unroll
        for (int ni = 0; ni < 8; ni++) {
            const int r0 = bm + wm * 64 + mi * 16 + lr;
            const int c0 = bn + wn * 64 + ni * 8 + lc * 2;
            float2 b01 = *(const float2*)(bias + c0);
            float2 v0 = make_float2(acc[mi][ni][0] + b01.x, acc[mi][ni][1] + b01.y);
            float2 v1 = make_float2(acc[mi][ni][2] + b01.x, acc[mi][ni][3] + b01.y);
            *(float2*)(C + (size_t)r0 * N + c0) = v0;
            *(float2*)(C + (size_t)(r0 + 8) * N + c0) = v1;
        }
    }
}

// ---------------------------------------------------------------------------
// comb[w][h][i][j] = mask[w][i][j] + bias_table[rel_index[i*49+j]][h]
// ---------------------------------------------------------------------------
__global__ __launch_bounds__(256) void comb_kernel(
    const float* __restrict__ mask, const float* __restrict__ bias_table,
    const int* __restrict__ rel_index, float* __restrict__ comb)
{
    const int total = NWIN * HEADS * NTOK * NTOK;
    int idx = blockIdx.x * 256 + threadIdx.x;
    if (idx < total) {
        const int ij = idx % (NTOK * NTOK);
        const int wh = idx / (NTOK * NTOK);
        const int h = wh & (HEADS - 1);
        const int w = wh >> 3;
        comb[idx] = mask[w * NTOK * NTOK + ij] + bias_table[rel_index[ij] * HEADS + h];
    }
}

// ---------------------------------------------------------------------------
// Register-resident-softmax bf16 attention (round-8 known good).
// ---------------------------------------------------------------------------
__global__ __launch_bounds__(128) void attn_reg_kernel(
    const float* __restrict__ qkv,       // [B, N, 768]
    const float* __restrict__ comb,      // [64][8][49][49]
    float* __restrict__ out)             // [B, N, 256] (tf32-rounded)
{
    __shared__ __align__(16) uint32_t sw[7104];
    uint32_t* Qh  = sw;            // 64 x 20
    uint32_t* Ql  = sw + 1280;
    uint32_t* Kh  = sw + 2560;     // 56 x 20
    uint32_t* Kl  = sw + 3680;
    uint32_t* Vth = sw + 4800;     // 32 x 36 (V transposed [d][j])
    uint32_t* Vtl = sw + 5952;

    const int b = blockIdx.x;
    const int h = blockIdx.y;
    const int tid = threadIdx.x;
    const int wid = tid >> 5;
    const int lane = tid & 31;
    const int lr = lane >> 2;
    const int lc = lane & 3;

    const float scale = 0.17677669529663687f;
    const float* base = qkv + (size_t)b * NTOK * 3 * DIM + h * HD;

    {
        __nv_bfloat16* vhH = (__nv_bfloat16*)Vth;
        __nv_bfloat16* vlH = (__nv_bfloat16*)Vtl;
        for (int e = tid; e < HD * 15; e += 128) {
            const int d = e / 15;
            const int j = NTOK + (e % 15);
            vhH[d * 72 + j] = __float2bfloat16(0.f);
            vlH[d * 72 + j] = __float2bfloat16(0.f);
        }
        for (int pe = tid; pe < NTOK * (HD / 2); pe += 128) {
            const int n = pe >> 4;
            const int dp = pe & 15;
            const int d = dp * 2;
            const float* row = base + (size_t)n * (3 * DIM) + d;
            float2 q2 = *(const float2*)(row);
            float2 k2 = *(const float2*)(row + DIM);
            float2 v2 = *(const float2*)(row + 2 * DIM);
            q2.x *= scale; q2.y *= scale;

            uint32_t hi, lo;
            split_pack_bf16(q2.x, q2.y, hi, lo);
            Qh[n * 20 + dp] = hi;
            Ql[n * 20 + dp] = lo;
            split_pack_bf16(k2.x, k2.y, hi, lo);
            Kh[n * 20 + dp] = hi;
            Kl[n * 20 + dp] = lo;

            __nv_bfloat16 vh0 = __float2bfloat16(v2.x);
            __nv_bfloat16 vh1 = __float2bfloat16(v2.y);
            __nv_bfloat16 vl0 = __float2bfloat16(v2.x - __bfloat162float(vh0));
            __nv_bfloat16 vl1 = __float2bfloat16(v2.y - __bfloat162float(vh1));
            vhH[d * 72 + n] = vh0;
            vhH[(d + 1) * 72 + n] = vh1;
            vlH[d * 72 + n] = vl0;
            vlH[(d + 1) * 72 + n] = vl1;
        }
    }
    __syncthreads();

    const int mr = wid * 16;

    float sacc[7][4] = {};
    #pragma unroll
    for (int kt = 0; kt < 2; kt++) {
        const int kw = kt * 8;
        uint32_t ah[4], al[4];
        ah[0] = Qh[(mr + lr) * 20 + kw + lc];
        ah[1] = Qh[(mr + 8 + lr) * 20 + kw + lc];
        ah[2] = Qh[(mr + lr) * 20 + kw + 4 + lc];
        ah[3] = Qh[(mr + 8 + lr) * 20 + kw + 4 + lc];
        al[0] = Ql[(mr + lr) * 20 + kw + lc];
        al[1] = Ql[(mr + 8 + lr) * 20 + kw + lc];
        al[2] = Ql[(mr + lr) * 20 + kw + 4 + lc];
        al[3] = Ql[(mr + 8 + lr) * 20 + kw + 4 + lc];

        #pragma unroll
        for (int nt = 0; nt < 7; nt++) {
            const int n0 = nt * 8;
            uint32_t bh[2], bl[2];
            bh[0] = Kh[(n0 + lr) * 20 + kw + lc];
            bh[1] = Kh[(n0 + lr) * 20 + kw + 4 + lc];
            bl[0] = Kl[(n0 + lr) * 20 + kw + lc];
            bl[1] = Kl[(n0 + lr) * 20 + kw + 4 + lc];
            mma_bf16(sacc[nt], ah, bh);
            mma_bf16(sacc[nt], al, bh);
            mma_bf16(sacc[nt], ah, bl);
        }
    }

    {
        const float* cb = comb + ((size_t)((b & (NWIN - 1)) * HEADS + h)) * (NTOK * NTOK);
        const int rA = mr + lr;
        const int rB = mr + 8 + lr;
        const bool okA = rA < NTOK;
        const bool okB = rB < NTOK;
        float mA = -CUDART_INF_F, mB = -CUDART_INF_F;

        #pragma unroll
        for (int nt = 0; nt < 7; nt++) {
            const int c0 = nt * 8 + 2 * lc;
            const bool ok0 = c0 < NTOK;
            const bool ok1 = (c0 + 1) < NTOK;
            float v0A = (okA && ok0) ? sacc[nt][0] + __ldg(cb + rA * NTOK + c0)     : -CUDART_INF_F;
            float v1A = (okA && ok1) ? sacc[nt][1] + __ldg(cb + rA * NTOK + c0 + 1) : -CUDART_INF_F;
            float v0B = (okB && ok0) ? sacc[nt][2] + __ldg(cb + rB * NTOK + c0)     : -CUDART_INF_F;
            float v1B = (okB && ok1) ? sacc[nt][3] + __ldg(cb + rB * NTOK + c0 + 1) : -CUDART_INF_F;
            sacc[nt][0] = v0A; sacc[nt][1] = v1A;
            sacc[nt][2] = v0B; sacc[nt][3] = v1B;
            mA = fmaxf(mA, fmaxf(v0A, v1A));
            mB = fmaxf(mB, fmaxf(v0B, v1B));
        }
        mA = fmaxf(mA, __shfl_xor_sync(0xffffffffu, mA, 1));
        mA = fmaxf(mA, __shfl_xor_sync(0xffffffffu, mA, 2));
        mB = fmaxf(mB, __shfl_xor_sync(0xffffffffu, mB, 1));
        mB = fmaxf(mB, __shfl_xor_sync(0xffffffffu, mB, 2));

        float sA = 0.f, sB = 0.f;
        #pragma unroll
        for (int nt = 0; nt < 7; nt++) {
            float e0A = __expf(sacc[nt][0] - mA);
            float e1A = __expf(sacc[nt][1] - mA);
            float e0B = __expf(sacc[nt][2] - mB);
            float e1B = __expf(sacc[nt][3] - mB);
            sacc[nt][0] = e0A; sacc[nt][1] = e1A;
            sacc[nt][2] = e0B; sacc[nt][3] = e1B;
            sA += e0A + e1A;
            sB += e0B + e1B;
        }
        sA += __shfl_xor_sync(0xffffffffu, sA, 1);
        sA += __shfl_xor_sync(0xffffffffu, sA, 2);
        sB += __shfl_xor_sync(0xffffffffu, sB, 1);
        sB += __shfl_xor_sync(0xffffffffu, sB, 2);
        const float invA = 1.f / sA;
        const float invB = 1.f / sB;
        #pragma unroll
        for (int nt = 0; nt < 7; nt++) {
            sacc[nt][0] *= invA; sacc[nt][1] *= invA;
            sacc[nt][2] *= invB; sacc[nt][3] *= invB;
        }
    }

    {
        float oacc[4][4] = {};
        #pragma unroll
        for (int kt = 0; kt < 4; kt++) {
            const int kw = kt * 8;
            const int t0 = 2 * kt;
            const int t1 = 2 * kt + 1;
            uint32_t ah[4], al[4];
            split_pack_bf16(sacc[t0][0], sacc[t0][1], ah[0], al[0]);
            split_pack_bf16(sacc[t0][2], sacc[t0][3], ah[1], al[1]);
            if (t1 < 7) {
                split_pack_bf16(sacc[t1][0], sacc[t1][1], ah[2], al[2]);
                split_pack_bf16(sacc[t1][2], sacc[t1][3], ah[3], al[3]);
            } else {
                ah[2] = ah[3] = al[2] = al[3] = 0u;
            }

            #pragma unroll
            for (int nt = 0; nt < 4; nt++) {
                const int n0 = nt * 8;
                uint32_t bh[2], bl[2];
                bh[0] = Vth[(n0 + lr) * 36 + kw + lc];
                bh[1] = Vth[(n0 + lr) * 36 + kw + 4 + lc];
                bl[0] = Vtl[(n0 + lr) * 36 + kw + lc];
                bl[1] = Vtl[(n0 + lr) * 36 + kw + 4 + lc];
                mma_bf16(oacc[nt], ah, bh);
                mma_bf16(oacc[nt], al, bh);
                mma_bf16(oacc[nt], ah, bl);
            }
        }

        const int r0 = mr + lr;
        const int r1 = mr + 8 + lr;
        #pragma unroll
        for (int nt = 0; nt < 4; nt++) {
            const int c0 = h * HD + nt * 8 + lc * 2;
            if (r0 < NTOK) {
                float2 v = make_float2(__uint_as_float(f2tf32(oacc[nt][0])),
                                       __uint_as_float(f2tf32(oacc[nt][1])));
                *(float2*)(out + ((size_t)b * NTOK + r0) * DIM + c0) = v;
            }
            if (r1 < NTOK) {
                float2 v = make_float2(__uint_as_float(f2tf32(oacc[nt][2])),
                                       __uint_as_float(f2tf32(oacc[nt][3])));
                *(float2*)(out + ((size_t)b * NTOK + r1) * DIM + c0) = v;
            }
        }
    }
}

// ---------------------------------------------------------------------------
extern "C" void kernel_launch(void* const* d_in, const int* in_sizes, int n_in,
                              void* d_out, int out_size)
{
    const float* x          = (const float*)d_in[0];
    const float* mask       = (const float*)d_in[1];
    const float* qkv_w      = (const float*)d_in[2];
    const float* qkv_b      = (const float*)d_in[3];
    const float* proj_w     = (const float*)d_in[4];
    const float* proj_b     = (const float*)d_in[5];
    const float* bias_table = (const float*)d_in[6];
    const int*   rel_index  = (const int*)d_in[7];
    float* out = (float*)d_out;

    float *qkv_buf, *ao_buf, *wq_buf, *wp_buf, *comb_buf;
    cudaGetSymbolAddress((void**)&qkv_buf, g_qkv);
    cudaGetSymbolAddress((void**)&ao_buf, g_ao);
    cudaGetSymbolAddress((void**)&wq_buf, g_wq);
    cudaGetSymbolAddress((void**)&wp_buf, g_wp);
    cudaGetSymbolAddress((void**)&comb_buf, g_comb);

    static bool attr_set = false;
    if (!attr_set) {
        cudaFuncSetAttribute(gemm_tf32_w64<true>,
                             cudaFuncAttributeMaxDynamicSharedMemorySize,
                             GEMM_SMEM_BYTES);
        cudaFuncSetAttribute(gemm_tf32_w64<false>,
                             cudaFuncAttributeMaxDynamicSharedMemorySize,
                             GEMM_SMEM_BYTES);
        attr_set = true;
    }

    const int M = BATCH * NTOK;   // 100352 = 128 * 784

    // 0a) tf32-round weights (small)
    {
        cvt_tf32_kernel<<<192, 256>>>((const float4*)qkv_w, (float4*)wq_buf,
                                      DIM * 3 * DIM / 4);
        cvt_tf32_kernel<<<64, 256>>>((const float4*)proj_w, (float4*)wp_buf,
                                     DIM * DIM / 4);
    }
    // 0b) combined bias+mask table
    {
        const int total = NWIN * HEADS * NTOK * NTOK;
        comb_kernel<<<(total + 255) / 256, 256>>>(mask, bias_table, rel_index, comb_buf);
    }
    // 1) QKV GEMM: raw f32 x, cvt in A-frag path
    {
        dim3 grid(3 * DIM / 128, M / 128);
        gemm_tf32_w64<true><<<grid, 128, GEMM_SMEM_BYTES>>>(x, wq_buf, qkv_b, qkv_buf,
                                                            M, 3 * DIM, DIM);
    }
    // 2) register-softmax attention
    {
        dim3 grid(BATCH, HEADS);
        attn_reg_kernel<<<grid, 128>>>(qkv_buf, comb_buf, ao_buf);
    }
    // 3) Proj GEMM: A already tf32-rounded
    {
        dim3 grid(DIM / 128, M / 128);
        gemm_tf32_w64<false><<<grid, 128, GEMM_SMEM_BYTES>>>(ao_buf, wp_buf, proj_b, out,
                                                             M, DIM, DIM);
    }
}